// round 15
// baseline (speedup 1.0000x reference)
#include <cuda_runtime.h>
#include <cuda_bf16.h>
#include <cuda_fp16.h>
#include <cstdint>

// Problem dims
#define BB 1024
#define TT 512
#define DD 128
#define HH 256
#define CCLS 2
#define NROWS 8
#define NCTA (BB / NROWS)   // 128 CTAs
#define NTHR 1024

// ---- fragment-packed fp16 weights (device global; no allocations allowed) ----
// Gates [0, 262144) u32, gate-fused layout (32 warps):
//   i = (((w*32 + s)*2 + v)*128 + t*4 + e,  u = v*2 + (e>>1), j2 = e&1
//   warp w owns h-cols [w*8, w*8+8); tile u = gate index (0=i,1=f,2=g,3=o)
//   k0 = s*16 + (t&3)*2 + j2*8,  N = u*256 + w*8 + (t>>2)
//   val = half2(W[k0][N], W[k0+1][N]),  W[k][N] = k<256 ? Wih[N][k] : Whh[N][k-256]
//   NOTE: i/f/o gate weights (u != 2) pre-scaled by 0.5 (exact in fp16):
//   sigmoid(x) = 0.5*tanh.approx(x/2) + 0.5 needs no runtime halving.
// Small GEMM fragments (uint2 per (lane,tile,step)):
//   G1 (gamma_h|gamma_x: K=128, N=384):  i=((cw*8+s)*3+cu)*64 + t*2 + j2, T=cw*3+cu
//   G2a (x_h: K=256,N=128):  i=((wl*16+s)*2+uu)*64 + t*2 + j2, T=wl*2+uu
//   G2b (alpha: K=256,N=128): same layout, separate base
//   G3 (z_h: K=128,N=128): i=(T*8+s)*64 + t*2 + j2
// G2a/G2b/G3 (160 KB) are staged into smem by the scan kernel's prologue.
#define SMG1  262144
#define SMG2A 286720
#define SMG2B 303104
#define SMG3  319488
#define WTB_TOTAL 327680
#define WSM_U32 40960          // G2a(16384) | G2b(16384) | G3(8192) in smem
__device__ uint32_t g_wtb_u[WTB_TOTAL];
// Combined gate bias bih+bhh (i/f/o pre-scaled by 0.5)
__device__ float g_gb[4 * HH];

// 1-MUFU tanh (sm_75+): max rel err ~2^-11
__device__ __forceinline__ float tanha(float x) {
    float y; asm("tanh.approx.f32 %0, %1;" : "=f"(y) : "f"(x)); return y;
}

// m16n8k16 HMMA; A rows 8-15 zero, c2/c3 discarded.
__device__ __forceinline__ void mma1(float& c0, float& c1, float& c2, float& c3,
                                     uint32_t a0, uint32_t a2, uint32_t b0, uint32_t b1) {
    asm volatile(
        "mma.sync.aligned.m16n8k16.row.col.f32.f16.f16.f32 "
        "{%0,%1,%2,%3}, {%4,%5,%6,%7}, {%8,%9}, {%0,%1,%2,%3};"
        : "+f"(c0), "+f"(c1), "+f"(c2), "+f"(c3)
        : "r"(a0), "r"(0u), "r"(a2), "r"(0u), "r"(b0), "r"(b1));
}

// ldmatrix x4: loads a0(s), a2(s), a0(s+1), a2(s+1) for two consecutive k-steps.
__device__ __forceinline__ void ldsm4(uint32_t addr, uint32_t& r0, uint32_t& r1,
                                      uint32_t& r2, uint32_t& r3) {
    asm volatile("ldmatrix.sync.aligned.m8n8.x4.shared.b16 {%0,%1,%2,%3}, [%4];"
        : "=r"(r0), "=r"(r1), "=r"(r2), "=r"(r3) : "r"(addr));
}

__device__ __forceinline__ uint32_t pack_pair(float lo, float hi) {
    uint32_t l = __half_as_ushort(__float2half_rn(lo));
    uint32_t h = __half_as_ushort(__float2half_rn(hi));
    return l | (h << 16);
}

// ---- fused prologue: all fragment packing + bias combine, ONE launch ----
#define PREP_TOTAL (WTB_TOTAL + 1024)
__global__ void prep_kernel(const float* __restrict__ Wdh, const float* __restrict__ Wdx,
                            const float* __restrict__ Wh,  const float* __restrict__ Wf,
                            const float* __restrict__ Wc,  const float* __restrict__ Wih,
                            const float* __restrict__ Whh, const float* __restrict__ bih,
                            const float* __restrict__ bhh) {
    int idx = blockIdx.x * blockDim.x + threadIdx.x;
    if (idx >= PREP_TOTAL) return;
    if (idx < 262144) {                    // gates, gate-fused coalesced layout
        int e = idx & 3, t = (idx >> 2) & 31, v = (idx >> 7) & 1;
        int s = (idx >> 8) & 31, w = (idx >> 13) & 31;
        int u = v * 2 + (e >> 1), j2 = e & 1;
        int k0 = s * 16 + (t & 3) * 2 + j2 * 8;
        int N  = u * 256 + w * 8 + (t >> 2);
        float lo, hi;
        if (k0 < 256) { lo = Wih[N * 256 + k0];       hi = Wih[N * 256 + k0 + 1]; }
        else          { lo = Whh[N * 256 + k0 - 256]; hi = Whh[N * 256 + k0 - 255]; }
        if (u != 2) { lo *= 0.5f; hi *= 0.5f; }     // i/f/o: fold sigmoid x/2
        g_wtb_u[idx] = pack_pair(lo, hi);
    } else if (idx < SMG2A) {              // G1
        int i = idx - SMG1;
        int j2 = i & 1, t = (i >> 1) & 31;
        int rest = i >> 6, uu = rest % 3, ws = rest / 3;
        int s = ws & 7, w = ws >> 3;
        int tile = w * 3 + uu;
        int n = tile * 8 + (t >> 2);
        int k0 = s * 16 + (t & 3) * 2 + j2 * 8;
        float lo, hi;
        if (n < 256) { lo = Wdh[n * 128 + k0]; hi = Wdh[n * 128 + k0 + 1]; }
        else { int n2 = n - 256; lo = Wdx[n2 * 128 + k0]; hi = Wdx[n2 * 128 + k0 + 1]; }
        g_wtb_u[idx] = pack_pair(lo, hi);
    } else if (idx < SMG2B) {              // G2a: Wh
        int i = idx - SMG2A;
        int j2 = i & 1, t = (i >> 1) & 31;
        int rest = i >> 6, uu = rest & 1, ws = rest >> 1;
        int s = ws & 15, w = ws >> 4;
        int n = (w * 2 + uu) * 8 + (t >> 2);
        int k0 = s * 16 + (t & 3) * 2 + j2 * 8;
        g_wtb_u[idx] = pack_pair(Wh[n * 256 + k0], Wh[n * 256 + k0 + 1]);
    } else if (idx < SMG3) {               // G2b: Wc (input = gx || m)
        int i = idx - SMG2B;
        int j2 = i & 1, t = (i >> 1) & 31;
        int rest = i >> 6, uu = rest & 1, ws = rest >> 1;
        int s = ws & 15, w = ws >> 4;
        int n = (w * 2 + uu) * 8 + (t >> 2);
        int k0 = s * 16 + (t & 3) * 2 + j2 * 8;
        g_wtb_u[idx] = pack_pair(Wc[n * 256 + k0], Wc[n * 256 + k0 + 1]);
    } else if (idx < WTB_TOTAL) {          // G3: Wf
        int i = idx - SMG3;
        int j2 = i & 1, t = (i >> 1) & 31;
        int rest = i >> 6, s = rest & 7, w = rest >> 3;
        int n = w * 8 + (t >> 2);
        int k0 = s * 16 + (t & 3) * 2 + j2 * 8;
        g_wtb_u[idx] = pack_pair(Wf[n * 128 + k0], Wf[n * 128 + k0 + 1]);
    } else {                               // combined gate bias (i/f/o halved)
        int i = idx - WTB_TOTAL;
        float b = bih[i] + bhh[i];
        int gate = i >> 8;                 // 0=i,1=f,2=g,3=o
        if (gate != 2) b *= 0.5f;
        g_gb[i] = b;
    }
}

// ---- persistent RITS scan: 128 CTAs x 8 rows, 1024 threads, 4 barriers/step ----
// smem layout:
//   wsm[40960 u32]      : G2a | G2b | G3 fragment tables (staged from g_wtb_u)
//   biasS[1792 floats]  : [0:1024) gb | [1024:1280) bdh | [1280:1408) bdx
//                         [1408:1536) bh | [1536:1664) bf | [1664:1792) bc
//   hs[2048] xs[1024] msa[1024] al[1024]
//   actH[8][PH] fp16 shadow per row:
//     W0 [0:512) / W1 [512:1024): parity gates A-window = c_c(128)|m(128)|hd(256)
//     [1024:1152) gx | [1152:1280) m_copy | [1280:1408) dsa | [1408:1536) x_c
#define PH 1544   // row stride 3088 B -> 4-bank shift per row (conflict-free LDSM)
#define OFF_GX 1024
#define OFF_MC 1152
#define OFF_DS 1280
#define OFF_XC 1408
#define BS_GB  0
#define BS_BDH 1024
#define BS_BDX 1280
#define BS_BH  1408
#define BS_BF  1536
#define BS_BC  1664
__global__ void __launch_bounds__(NTHR, 1) rits_kernel(
    const float* __restrict__ values, const int* __restrict__ masks, const float* __restrict__ deltas,
    const float* __restrict__ bdh, const float* __restrict__ bdx,
    const float* __restrict__ bh,  const float* __restrict__ bf_,
    const float* __restrict__ bc,
    const float* __restrict__ Wo,  const float* __restrict__ bo,
    float* __restrict__ out)
{
    extern __shared__ char sm_raw[];
    uint32_t* wsm = (uint32_t*)sm_raw;          // 40960 u32
    float* biasS = (float*)(wsm + WSM_U32);     // 1792 floats
    float* hs  = biasS + 1792;    // [H*8]
    float* xs  = hs  + 2048;      // [D*8]
    float* msa = xs  + 1024;      // [D*8]
    float* al  = msa + 1024;      // [D*8]  alpha
    __half* actH = (__half*)(al + 1024);        // [8][PH]

    const int j = threadIdx.x;
    const int w = j >> 5, tl = j & 31;
    const int rr = tl >> 2, c4 = tl & 3;
    const int rowbase = blockIdx.x * NROWS;
    float* out_imp = out + BB * CCLS;

    // LDSM lane address base (bytes): row = tl&7, matrix idx = (tl>>3)&3 -> +0/8/16/24 halves
    const uint32_t actB = (uint32_t)__cvta_generic_to_shared(actH);
    const uint32_t lds_lane = ((tl & 7) * PH + ((tl >> 3) & 3) * 8) * 2;

    // ---- prologue: stage small-GEMM weights + biases into smem ----
    {
        const uint4* src = (const uint4*)(g_wtb_u + SMG2A);
        uint4* dst = (uint4*)wsm;
        #pragma unroll
        for (int i = 0; i < 10; ++i) dst[j + i * NTHR] = src[j + i * NTHR];
    }
    // gate bias: every thread one element (BUGFIX R14: this is NOT an else-chain
    // with the small biases below — all 1024 threads take this store)
    biasS[BS_GB + j] = g_gb[j];
    // small biases: threads 0-767 stage the 768 remaining floats
    if (j < 256)      biasS[BS_BDH + j]       = bdh[j];
    else if (j < 384) biasS[BS_BDX + (j-256)] = bdx[j - 256];
    else if (j < 512) biasS[BS_BH  + (j-384)] = bh[j - 384];
    else if (j < 640) biasS[BS_BF  + (j-512)] = bf_[j - 512];
    else if (j < 768) biasS[BS_BC  + (j-640)] = bc[j - 640];
    for (int i = j; i < 2048; i += NTHR) { hs[i] = 0.f; }

    // cell state lives in registers: phase-5 epilogue thread owns (n0..n0+1, rr) forever
    float csr[2] = {0.f, 0.f};

    // input prefetch (1 elem/thread)
    const int r1 = j >> 7, k1 = j & 127;
    float pv, pm, pd;
    {
        int g = rowbase * (TT * DD) + r1 * (TT * DD) + k1;
        pv = values[g]; pm = (float)masks[g]; pd = deltas[g];
    }
    // commit step 0 (window 0)
    {
        int si = k1 * 8 + r1;
        xs[si] = pv; msa[si] = pm;
        __half mh = __float2half(pm);
        actH[r1 * PH + OFF_MC + k1] = mh;
        actH[r1 * PH + 128 + k1] = mh;                 // m_gates, window 0
        actH[r1 * PH + OFF_DS + k1] = __float2half(pd);
    }
    // prefetch step 1
    {
        int g = rowbase * (TT * DD) + r1 * (TT * DD) + DD + k1;
        pv = values[g]; pm = (float)masks[g]; pd = deltas[g];
    }
    __syncthreads();

    for (int t = 0; t < TT; ++t) {
        const int Wp = (t & 1) * 512;
        const int Wq = 512 - Wp;

        // ---- phase 2 (G1): gamma_h | gamma_x; tiles T=w (all), T=32+w (w<16) ----
        {
            const uint2* fb = (const uint2*)(g_wtb_u + SMG1);
            float acc0 = 0.f, acc1 = 0.f, accB0 = 0.f, accB1 = 0.f;
            float d2 = 0.f, d3 = 0.f;
            const int cw1 = w / 3, cu1 = w - cw1 * 3;
            const int T2 = 32 + w;
            const int cw2 = T2 / 3, cu2 = T2 - cw2 * 3;
            const bool two = (w < 16);
            const uint32_t abase = actB + lds_lane + OFF_DS * 2;
            #pragma unroll
            for (int s2 = 0; s2 < 4; ++s2) {
                uint32_t a0, a2, a0b, a2b;
                ldsm4(abase + s2 * 64, a0, a2, a0b, a2b);
                int s = s2 * 2;
                uint2 b0 = fb[((cw1 * 8 + s) * 3 + cu1) * 32 + tl];
                uint2 b1 = fb[((cw1 * 8 + s + 1) * 3 + cu1) * 32 + tl];
                mma1(acc0, acc1, d2, d3, a0, a2, b0.x, b0.y);
                mma1(acc0, acc1, d2, d3, a0b, a2b, b1.x, b1.y);
                if (two) {
                    uint2 c0 = fb[((cw2 * 8 + s) * 3 + cu2) * 32 + tl];
                    uint2 c1 = fb[((cw2 * 8 + s + 1) * 3 + cu2) * 32 + tl];
                    mma1(accB0, accB1, d2, d3, a0, a2, c0.x, c0.y);
                    mma1(accB0, accB1, d2, d3, a0b, a2b, c1.x, c1.y);
                }
            }
            {
                int n0 = w * 8 + c4 * 2;
                #pragma unroll
                for (int c = 0; c < 2; ++c) {
                    int n = n0 + c;
                    float v = (c == 0) ? acc0 : acc1;
                    float gam = __expf(-fmaxf(v + biasS[BS_BDH + n], 0.f));
                    float hv = hs[n * 8 + rr] * gam;
                    actH[rr * PH + Wp + 256 + n] = __float2half(hv);
                }
            }
            if (two) {
                int n0 = T2 * 8 - 256 + c4 * 2;
                #pragma unroll
                for (int c = 0; c < 2; ++c) {
                    int n2 = n0 + c;
                    float v = (c == 0) ? accB0 : accB1;
                    float gxv = __expf(-fmaxf(v + biasS[BS_BDX + n2], 0.f));
                    actH[rr * PH + OFF_GX + n2] = __float2half(gxv);
                }
            }
        }
        __syncthreads();                           // B2

        // ---- phase 3 (G2): x_h + x_c (warps 0-15) | alpha (warps 16-31) ----
        float xh0 = 0.f, xh1 = 0.f;                // live across B3 into phase 4
        {
            const bool isA = (w < 16);
            const int T = isA ? w : (w - 16);
            const int wl = T >> 1, uu = T & 1;
            const uint32_t abase = actB + lds_lane
                                 + (isA ? (Wp + 256) : OFF_GX) * 2;
            const uint2* fb = (const uint2*)(wsm + (isA ? 0 : 16384));   // smem-staged
            float acc0 = 0.f, acc1 = 0.f, d2 = 0.f, d3 = 0.f;
            #pragma unroll
            for (int s2 = 0; s2 < 8; ++s2) {
                uint32_t a0, a2, a0b, a2b;
                ldsm4(abase + s2 * 64, a0, a2, a0b, a2b);
                int s = s2 * 2;
                uint2 b0 = fb[((wl * 16 + s) * 2 + uu) * 32 + tl];
                uint2 b1 = fb[((wl * 16 + s + 1) * 2 + uu) * 32 + tl];
                mma1(acc0, acc1, d2, d3, a0, a2, b0.x, b0.y);
                mma1(acc0, acc1, d2, d3, a0b, a2b, b1.x, b1.y);
            }
            int n0 = T * 8 + c4 * 2;
            if (isA) {
                xh0 = acc0 + biasS[BS_BH + n0];
                xh1 = acc1 + biasS[BS_BH + n0 + 1];
                float m0 = msa[n0 * 8 + rr],       x0 = xs[n0 * 8 + rr];
                float m1 = msa[(n0 + 1) * 8 + rr], x1 = xs[(n0 + 1) * 8 + rr];
                actH[rr * PH + OFF_XC + n0]     = __float2half(m0 * x0 + (1.f - m0) * xh0);
                actH[rr * PH + OFF_XC + n0 + 1] = __float2half(m1 * x1 + (1.f - m1) * xh1);
            } else {
                al[n0 * 8 + rr]       = acc0 + biasS[BS_BC + n0];
                al[(n0 + 1) * 8 + rr] = acc1 + biasS[BS_BC + n0 + 1];
            }
        }
        __syncthreads();                           // B3

        // ---- phase 4 (G3): z_h + c_h + c_c + imputation (warps 0-15) ----
        if (w < 16) {
            float acc0 = 0.f, acc1 = 0.f, d2 = 0.f, d3 = 0.f;
            const uint32_t abase = actB + lds_lane + OFF_XC * 2;
            const uint2* fb = (const uint2*)(wsm + 32768);               // smem-staged
            #pragma unroll
            for (int s2 = 0; s2 < 4; ++s2) {
                uint32_t a0, a2, a0b, a2b;
                ldsm4(abase + s2 * 64, a0, a2, a0b, a2b);
                int s = s2 * 2;
                uint2 b0 = fb[(w * 8 + s) * 32 + tl];
                uint2 b1 = fb[(w * 8 + s + 1) * 32 + tl];
                mma1(acc0, acc1, d2, d3, a0, a2, b0.x, b0.y);
                mma1(acc0, acc1, d2, d3, a0b, a2b, b1.x, b1.y);
            }
            int n0 = w * 8 + c4 * 2;
            const int gbase = rowbase * (TT * DD) + rr * (TT * DD) + t * DD;
            float cc2[2];
            #pragma unroll
            for (int c = 0; c < 2; ++c) {
                int n = n0 + c;
                float zv = ((c == 0) ? acc0 : acc1) + biasS[BS_BF + n];
                float xhv = (c == 0) ? xh0 : xh1;
                float a = al[n * 8 + rr];
                float mv = msa[n * 8 + rr], xv = xs[n * 8 + rr];
                float ch = a * zv + (1.f - a) * xhv;
                float cc = mv * xv + (1.f - mv) * ch;
                actH[rr * PH + Wp + n] = __float2half(cc);
                cc2[c] = cc;
            }
            *(float2*)&out_imp[gbase + n0] = make_float2(cc2[0], cc2[1]);
        }
        __syncthreads();                           // B4

        // ---- phase 5: commit t+1 inputs, gates MMA, fused LSTM update ----
        {
            // head: commit step t+1 into parity window Wq + side regions
            if (t + 1 < TT) {
                int si = k1 * 8 + r1;
                xs[si] = pv; msa[si] = pm;
                __half mh = __float2half(pm);
                actH[r1 * PH + OFF_MC + k1] = mh;
                actH[r1 * PH + Wq + 128 + k1] = mh;
                actH[r1 * PH + OFF_DS + k1] = __float2half(pd);
            }
            if (t + 2 < TT) {
                int g = rowbase * (TT * DD) + r1 * (TT * DD) + (t + 2) * DD + k1;
                pv = values[g]; pm = (float)masks[g]; pd = deltas[g];
            }

            float acc[4][2];                       // u = gate (i,f,g,o)
            #pragma unroll
            for (int u = 0; u < 4; ++u) { acc[u][0] = 0.f; acc[u][1] = 0.f; }
            float d2 = 0.f, d3 = 0.f;
            const uint4* fragbase = (const uint4*)g_wtb_u + (size_t)w * 2048 + tl;
            const uint32_t abase = actB + lds_lane + Wp * 2;
            #pragma unroll 8
            for (int s2 = 0; s2 < 16; ++s2) {
                uint32_t a0, a2, a0b, a2b;
                ldsm4(abase + s2 * 64, a0, a2, a0b, a2b);
                int s = s2 * 2;
                const uint4* wp0 = fragbase + s * 64;
                uint4 q0 = wp0[0], q1 = wp0[32];
                mma1(acc[0][0], acc[0][1], d2, d3, a0, a2, q0.x, q0.y);
                mma1(acc[1][0], acc[1][1], d2, d3, a0, a2, q0.z, q0.w);
                mma1(acc[2][0], acc[2][1], d2, d3, a0, a2, q1.x, q1.y);
                mma1(acc[3][0], acc[3][1], d2, d3, a0, a2, q1.z, q1.w);
                const uint4* wp1 = fragbase + (s + 1) * 64;
                uint4 q2 = wp1[0], q3 = wp1[32];
                mma1(acc[0][0], acc[0][1], d2, d3, a0b, a2b, q2.x, q2.y);
                mma1(acc[1][0], acc[1][1], d2, d3, a0b, a2b, q2.z, q2.w);
                mma1(acc[2][0], acc[2][1], d2, d3, a0b, a2b, q3.x, q3.y);
                mma1(acc[3][0], acc[3][1], d2, d3, a0b, a2b, q3.z, q3.w);
            }
            int n0 = w * 8 + c4 * 2;
            #pragma unroll
            for (int c = 0; c < 2; ++c) {
                int n = n0 + c;
                // i/f/o pre-activations are pre-halved (weights+bias); sig = 0.5*tanh+0.5
                float ig = fmaf(tanha(acc[0][c] + biasS[BS_GB + n]),       0.5f, 0.5f);
                float fg = fmaf(tanha(acc[1][c] + biasS[BS_GB + 256 + n]), 0.5f, 0.5f);
                float gg = tanha(acc[2][c] + biasS[BS_GB + 512 + n]);
                float og = fmaf(tanha(acc[3][c] + biasS[BS_GB + 768 + n]), 0.5f, 0.5f);
                float cn = fg * csr[c] + ig * gg;
                csr[c] = cn;
                hs[n * 8 + rr] = og * tanha(cn);
            }
        }
        __syncthreads();                           // B5
    }

    // ---- final: y_h = h@Wo.T + bo ----
    if (j < NROWS * CCLS) {
        int r = j >> 1, cl = j & 1;
        float acc = bo[cl];
        #pragma unroll 8
        for (int k = 0; k < HH; ++k) acc += hs[k * 8 + r] * Wo[cl * HH + k];
        out[(rowbase + r) * CCLS + cl] = acc;
    }
}

extern "C" void kernel_launch(void* const* d_in, const int* in_sizes, int n_in,
                              void* d_out, int out_size) {
    const float* values = (const float*)d_in[0];
    const int*   masks  = (const int*)  d_in[1];
    const float* deltas = (const float*)d_in[2];
    const float* Wdh = (const float*)d_in[3];
    const float* bdh = (const float*)d_in[4];
    const float* Wdx = (const float*)d_in[5];
    const float* bdx = (const float*)d_in[6];
    const float* Wh  = (const float*)d_in[7];
    const float* bh  = (const float*)d_in[8];
    const float* Wf  = (const float*)d_in[9];
    const float* bf_ = (const float*)d_in[10];
    const float* Wc  = (const float*)d_in[11];
    const float* bc  = (const float*)d_in[12];
    const float* Wih = (const float*)d_in[13];
    const float* bih = (const float*)d_in[14];
    const float* Whh = (const float*)d_in[15];
    const float* bhh = (const float*)d_in[16];
    const float* Wo  = (const float*)d_in[17];
    const float* bo  = (const float*)d_in[18];
    float* out = (float*)d_out;

    prep_kernel<<<(PREP_TOTAL + 255) / 256, 256>>>(Wdh, Wdx, Wh, Wf, Wc, Wih, Whh, bih, bhh);

    // smem: wsm 163840 B + biasS 7168 B + floats 20480 B + actH 24704 B = 216192 B
    size_t smem_bytes = (size_t)WSM_U32 * 4 + 1792 * 4 + 5120 * 4 + 8 * PH * sizeof(__half);
    cudaFuncSetAttribute(rits_kernel, cudaFuncAttributeMaxDynamicSharedMemorySize,
                         (int)smem_bytes);
    rits_kernel<<<NCTA, NTHR, smem_bytes>>>(values, masks, deltas,
                                            bdh, bdx, bh, bf_, bc,
                                            Wo, bo, out);
}

// round 16
// speedup vs baseline: 1.0053x; 1.0053x over previous
#include <cuda_runtime.h>
#include <cuda_bf16.h>
#include <cuda_fp16.h>
#include <cstdint>

// Problem dims
#define BB 1024
#define TT 512
#define DD 128
#define HH 256
#define CCLS 2
#define NROWS 8
#define NCTA (BB / NROWS)   // 128 CTAs
#define NTHR 1024

// ---- fragment-packed fp16 weights (device global; no allocations allowed) ----
// Gates [0, 262144) u32, gate-fused layout (32 warps):
//   i = (((w*32 + s)*2 + v)*128 + t*4 + e,  u = v*2 + (e>>1), j2 = e&1
//   warp w owns h-cols [w*8, w*8+8); tile u = gate index (0=i,1=f,2=g,3=o)
//   k0 = s*16 + (t&3)*2 + j2*8,  N = u*256 + w*8 + (t>>2)
//   val = half2(W[k0][N], W[k0+1][N]),  W[k][N] = k<256 ? Wih[N][k] : Whh[N][k-256]
//   NOTE: i/f/o gate weights (u != 2) pre-scaled by 0.5 (exact in fp16):
//   sigmoid(x) = 0.5*tanh.approx(x/2) + 0.5 needs no runtime halving.
// Small GEMM fragments (uint2 per (lane,tile,step)):
//   G1 (gamma_h|gamma_x: K=128, N=384):  i=((cw*8+s)*3+cu)*64 + t*2 + j2, T=cw*3+cu
//   G2a (x_h: K=256,N=128):  i=((wl*16+s)*2+uu)*64 + t*2 + j2, T=wl*2+uu
//   G2b (alpha: K=256,N=128): same layout, separate base
//   G3 (z_h: K=128,N=128): i=(T*8+s)*64 + t*2 + j2
// G2a/G2b/G3 (160 KB) are staged into smem by the scan kernel's prologue.
#define SMG1  262144
#define SMG2A 286720
#define SMG2B 303104
#define SMG3  319488
#define WTB_TOTAL 327680
#define WSM_U32 40960          // G2a(16384) | G2b(16384) | G3(8192) in smem
__device__ uint32_t g_wtb_u[WTB_TOTAL];
// Combined gate bias bih+bhh (i/f/o pre-scaled by 0.5)
__device__ float g_gb[4 * HH];

// 1-MUFU tanh (sm_75+): max rel err ~2^-11
__device__ __forceinline__ float tanha(float x) {
    float y; asm("tanh.approx.f32 %0, %1;" : "=f"(y) : "f"(x)); return y;
}

// m16n8k16 HMMA; A rows 8-15 zero, c2/c3 discarded.
__device__ __forceinline__ void mma1(float& c0, float& c1, float& c2, float& c3,
                                     uint32_t a0, uint32_t a2, uint32_t b0, uint32_t b1) {
    asm volatile(
        "mma.sync.aligned.m16n8k16.row.col.f32.f16.f16.f32 "
        "{%0,%1,%2,%3}, {%4,%5,%6,%7}, {%8,%9}, {%0,%1,%2,%3};"
        : "+f"(c0), "+f"(c1), "+f"(c2), "+f"(c3)
        : "r"(a0), "r"(0u), "r"(a2), "r"(0u), "r"(b0), "r"(b1));
}

// ldmatrix x4: loads a0(s), a2(s), a0(s+1), a2(s+1) for two consecutive k-steps.
__device__ __forceinline__ void ldsm4(uint32_t addr, uint32_t& r0, uint32_t& r1,
                                      uint32_t& r2, uint32_t& r3) {
    asm volatile("ldmatrix.sync.aligned.m8n8.x4.shared.b16 {%0,%1,%2,%3}, [%4];"
        : "=r"(r0), "=r"(r1), "=r"(r2), "=r"(r3) : "r"(addr));
}

__device__ __forceinline__ uint32_t pack_pair(float lo, float hi) {
    uint32_t l = __half_as_ushort(__float2half_rn(lo));
    uint32_t h = __half_as_ushort(__float2half_rn(hi));
    return l | (h << 16);
}

// ---- fused prologue: all fragment packing + bias combine, ONE launch ----
#define PREP_TOTAL (WTB_TOTAL + 1024)
__global__ void prep_kernel(const float* __restrict__ Wdh, const float* __restrict__ Wdx,
                            const float* __restrict__ Wh,  const float* __restrict__ Wf,
                            const float* __restrict__ Wc,  const float* __restrict__ Wih,
                            const float* __restrict__ Whh, const float* __restrict__ bih,
                            const float* __restrict__ bhh) {
    int idx = blockIdx.x * blockDim.x + threadIdx.x;
    if (idx >= PREP_TOTAL) return;
    if (idx < 262144) {                    // gates, gate-fused coalesced layout
        int e = idx & 3, t = (idx >> 2) & 31, v = (idx >> 7) & 1;
        int s = (idx >> 8) & 31, w = (idx >> 13) & 31;
        int u = v * 2 + (e >> 1), j2 = e & 1;
        int k0 = s * 16 + (t & 3) * 2 + j2 * 8;
        int N  = u * 256 + w * 8 + (t >> 2);
        float lo, hi;
        if (k0 < 256) { lo = Wih[N * 256 + k0];       hi = Wih[N * 256 + k0 + 1]; }
        else          { lo = Whh[N * 256 + k0 - 256]; hi = Whh[N * 256 + k0 - 255]; }
        if (u != 2) { lo *= 0.5f; hi *= 0.5f; }     // i/f/o: fold sigmoid x/2
        g_wtb_u[idx] = pack_pair(lo, hi);
    } else if (idx < SMG2A) {              // G1
        int i = idx - SMG1;
        int j2 = i & 1, t = (i >> 1) & 31;
        int rest = i >> 6, uu = rest % 3, ws = rest / 3;
        int s = ws & 7, w = ws >> 3;
        int tile = w * 3 + uu;
        int n = tile * 8 + (t >> 2);
        int k0 = s * 16 + (t & 3) * 2 + j2 * 8;
        float lo, hi;
        if (n < 256) { lo = Wdh[n * 128 + k0]; hi = Wdh[n * 128 + k0 + 1]; }
        else { int n2 = n - 256; lo = Wdx[n2 * 128 + k0]; hi = Wdx[n2 * 128 + k0 + 1]; }
        g_wtb_u[idx] = pack_pair(lo, hi);
    } else if (idx < SMG2B) {              // G2a: Wh
        int i = idx - SMG2A;
        int j2 = i & 1, t = (i >> 1) & 31;
        int rest = i >> 6, uu = rest & 1, ws = rest >> 1;
        int s = ws & 15, w = ws >> 4;
        int n = (w * 2 + uu) * 8 + (t >> 2);
        int k0 = s * 16 + (t & 3) * 2 + j2 * 8;
        g_wtb_u[idx] = pack_pair(Wh[n * 256 + k0], Wh[n * 256 + k0 + 1]);
    } else if (idx < SMG3) {               // G2b: Wc (input = gx || m)
        int i = idx - SMG2B;
        int j2 = i & 1, t = (i >> 1) & 31;
        int rest = i >> 6, uu = rest & 1, ws = rest >> 1;
        int s = ws & 15, w = ws >> 4;
        int n = (w * 2 + uu) * 8 + (t >> 2);
        int k0 = s * 16 + (t & 3) * 2 + j2 * 8;
        g_wtb_u[idx] = pack_pair(Wc[n * 256 + k0], Wc[n * 256 + k0 + 1]);
    } else if (idx < WTB_TOTAL) {          // G3: Wf
        int i = idx - SMG3;
        int j2 = i & 1, t = (i >> 1) & 31;
        int rest = i >> 6, s = rest & 7, w = rest >> 3;
        int n = w * 8 + (t >> 2);
        int k0 = s * 16 + (t & 3) * 2 + j2 * 8;
        g_wtb_u[idx] = pack_pair(Wf[n * 128 + k0], Wf[n * 128 + k0 + 1]);
    } else {                               // combined gate bias (i/f/o halved)
        int i = idx - WTB_TOTAL;
        float b = bih[i] + bhh[i];
        int gate = i >> 8;                 // 0=i,1=f,2=g,3=o
        if (gate != 2) b *= 0.5f;
        g_gb[i] = b;
    }
}

// ---- persistent RITS scan: 128 CTAs x 8 rows, 1024 threads, 4 barriers/step ----
// smem layout:
//   wsm[40960 u32]      : G2a | G2b | G3 fragment tables (staged from g_wtb_u)
//   biasS[1792 floats]  : [0:1024) gb | [1024:1280) bdh | [1280:1408) bdx
//                         [1408:1536) bh | [1536:1664) bf | [1664:1792) bc
//   hs[2048] xs[1024] msa[1024] al[1024]
//   actH[8][PH] fp16 shadow per row:
//     W0 [0:512) / W1 [512:1024): parity gates A-window = c_c(128)|m(128)|hd(256)
//     [1024:1152) gx | [1152:1280) m_copy | [1280:1408) dsa | [1408:1536) x_c
#define PH 1544   // row stride 3088 B -> 4-bank shift per row (conflict-free LDSM)
#define OFF_GX 1024
#define OFF_MC 1152
#define OFF_DS 1280
#define OFF_XC 1408
#define BS_GB  0
#define BS_BDH 1024
#define BS_BDX 1280
#define BS_BH  1408
#define BS_BF  1536
#define BS_BC  1664
__global__ void __launch_bounds__(NTHR, 1) rits_kernel(
    const float* __restrict__ values, const int* __restrict__ masks, const float* __restrict__ deltas,
    const float* __restrict__ bdh, const float* __restrict__ bdx,
    const float* __restrict__ bh,  const float* __restrict__ bf_,
    const float* __restrict__ bc,
    const float* __restrict__ Wo,  const float* __restrict__ bo,
    float* __restrict__ out)
{
    extern __shared__ char sm_raw[];
    uint32_t* wsm = (uint32_t*)sm_raw;          // 40960 u32
    float* biasS = (float*)(wsm + WSM_U32);     // 1792 floats
    float* hs  = biasS + 1792;    // [H*8]
    float* xs  = hs  + 2048;      // [D*8]
    float* msa = xs  + 1024;      // [D*8]
    float* al  = msa + 1024;      // [D*8]  alpha
    __half* actH = (__half*)(al + 1024);        // [8][PH]

    const int j = threadIdx.x;
    const int w = j >> 5, tl = j & 31;
    const int rr = tl >> 2, c4 = tl & 3;
    const int rowbase = blockIdx.x * NROWS;
    float* out_imp = out + BB * CCLS;

    // LDSM lane address base (bytes): row = tl&7, matrix idx = (tl>>3)&3 -> +0/8/16/24 halves
    const uint32_t actB = (uint32_t)__cvta_generic_to_shared(actH);
    const uint32_t lds_lane = ((tl & 7) * PH + ((tl >> 3) & 3) * 8) * 2;

    // ---- prologue: stage small-GEMM weights + biases into smem ----
    {
        const uint4* src = (const uint4*)(g_wtb_u + SMG2A);
        uint4* dst = (uint4*)wsm;
        #pragma unroll
        for (int i = 0; i < 10; ++i) dst[j + i * NTHR] = src[j + i * NTHR];
    }
    // gate bias: every thread one element (separate store, NOT else-chained)
    biasS[BS_GB + j] = g_gb[j];
    // small biases: threads 0-767 stage the 768 remaining floats
    if (j < 256)      biasS[BS_BDH + j]       = bdh[j];
    else if (j < 384) biasS[BS_BDX + (j-256)] = bdx[j - 256];
    else if (j < 512) biasS[BS_BH  + (j-384)] = bh[j - 384];
    else if (j < 640) biasS[BS_BF  + (j-512)] = bf_[j - 512];
    else if (j < 768) biasS[BS_BC  + (j-640)] = bc[j - 640];
    for (int i = j; i < 2048; i += NTHR) { hs[i] = 0.f; }

    // cell state lives in registers: phase-5 epilogue thread owns (n0..n0+1, rr) forever
    float csr[2] = {0.f, 0.f};

    // input prefetch (1 elem/thread)
    const int r1 = j >> 7, k1 = j & 127;
    float pv, pm, pd;
    {
        int g = rowbase * (TT * DD) + r1 * (TT * DD) + k1;
        pv = values[g]; pm = (float)masks[g]; pd = deltas[g];
    }
    // commit step 0 (window 0)
    {
        int si = k1 * 8 + r1;
        xs[si] = pv; msa[si] = pm;
        __half mh = __float2half(pm);
        actH[r1 * PH + OFF_MC + k1] = mh;
        actH[r1 * PH + 128 + k1] = mh;                 // m_gates, window 0
        actH[r1 * PH + OFF_DS + k1] = __float2half(pd);
    }
    // prefetch step 1
    {
        int g = rowbase * (TT * DD) + r1 * (TT * DD) + DD + k1;
        pv = values[g]; pm = (float)masks[g]; pd = deltas[g];
    }
    __syncthreads();

    for (int t = 0; t < TT; ++t) {
        const int Wp = (t & 1) * 512;
        const int Wq = 512 - Wp;

        // ---- phase 2 (G1): gamma_h | gamma_x; tiles T=w (all), T=32+w (w<16) ----
        {
            const uint2* fb = (const uint2*)(g_wtb_u + SMG1);
            float acc0 = 0.f, acc1 = 0.f, accB0 = 0.f, accB1 = 0.f;
            float d2 = 0.f, d3 = 0.f;
            const int cw1 = w / 3, cu1 = w - cw1 * 3;
            const int T2 = 32 + w;
            const int cw2 = T2 / 3, cu2 = T2 - cw2 * 3;
            const bool two = (w < 16);
            const uint32_t abase = actB + lds_lane + OFF_DS * 2;
            #pragma unroll
            for (int s2 = 0; s2 < 4; ++s2) {
                uint32_t a0, a2, a0b, a2b;
                ldsm4(abase + s2 * 64, a0, a2, a0b, a2b);
                int s = s2 * 2;
                uint2 b0 = fb[((cw1 * 8 + s) * 3 + cu1) * 32 + tl];
                uint2 b1 = fb[((cw1 * 8 + s + 1) * 3 + cu1) * 32 + tl];
                mma1(acc0, acc1, d2, d3, a0, a2, b0.x, b0.y);
                mma1(acc0, acc1, d2, d3, a0b, a2b, b1.x, b1.y);
                if (two) {
                    uint2 c0 = fb[((cw2 * 8 + s) * 3 + cu2) * 32 + tl];
                    uint2 c1 = fb[((cw2 * 8 + s + 1) * 3 + cu2) * 32 + tl];
                    mma1(accB0, accB1, d2, d3, a0, a2, c0.x, c0.y);
                    mma1(accB0, accB1, d2, d3, a0b, a2b, c1.x, c1.y);
                }
            }
            {
                int n0 = w * 8 + c4 * 2;
                #pragma unroll
                for (int c = 0; c < 2; ++c) {
                    int n = n0 + c;
                    float v = (c == 0) ? acc0 : acc1;
                    float gam = __expf(-fmaxf(v + biasS[BS_BDH + n], 0.f));
                    float hv = hs[n * 8 + rr] * gam;
                    actH[rr * PH + Wp + 256 + n] = __float2half(hv);
                }
            }
            if (two) {
                int n0 = T2 * 8 - 256 + c4 * 2;
                #pragma unroll
                for (int c = 0; c < 2; ++c) {
                    int n2 = n0 + c;
                    float v = (c == 0) ? accB0 : accB1;
                    float gxv = __expf(-fmaxf(v + biasS[BS_BDX + n2], 0.f));
                    actH[rr * PH + OFF_GX + n2] = __float2half(gxv);
                }
            }
        }
        __syncthreads();                           // B2

        // ---- phase 3 (G2): x_h + x_c (warps 0-15) | alpha (warps 16-31) ----
        float xh0 = 0.f, xh1 = 0.f;                // live across B3 into phase 4
        {
            const bool isA = (w < 16);
            const int T = isA ? w : (w - 16);
            const int wl = T >> 1, uu = T & 1;
            const uint32_t abase = actB + lds_lane
                                 + (isA ? (Wp + 256) : OFF_GX) * 2;
            const uint2* fb = (const uint2*)(wsm + (isA ? 0 : 16384));   // smem-staged
            float acc0 = 0.f, acc1 = 0.f, d2 = 0.f, d3 = 0.f;
            #pragma unroll
            for (int s2 = 0; s2 < 8; ++s2) {
                uint32_t a0, a2, a0b, a2b;
                ldsm4(abase + s2 * 64, a0, a2, a0b, a2b);
                int s = s2 * 2;
                uint2 b0 = fb[((wl * 16 + s) * 2 + uu) * 32 + tl];
                uint2 b1 = fb[((wl * 16 + s + 1) * 2 + uu) * 32 + tl];
                mma1(acc0, acc1, d2, d3, a0, a2, b0.x, b0.y);
                mma1(acc0, acc1, d2, d3, a0b, a2b, b1.x, b1.y);
            }
            int n0 = T * 8 + c4 * 2;
            if (isA) {
                xh0 = acc0 + biasS[BS_BH + n0];
                xh1 = acc1 + biasS[BS_BH + n0 + 1];
                float m0 = msa[n0 * 8 + rr],       x0 = xs[n0 * 8 + rr];
                float m1 = msa[(n0 + 1) * 8 + rr], x1 = xs[(n0 + 1) * 8 + rr];
                actH[rr * PH + OFF_XC + n0]     = __float2half(m0 * x0 + (1.f - m0) * xh0);
                actH[rr * PH + OFF_XC + n0 + 1] = __float2half(m1 * x1 + (1.f - m1) * xh1);
            } else {
                al[n0 * 8 + rr]       = acc0 + biasS[BS_BC + n0];
                al[(n0 + 1) * 8 + rr] = acc1 + biasS[BS_BC + n0 + 1];
            }
        }
        __syncthreads();                           // B3

        // ---- phase 4 (G3): z_h + c_h + c_c + imputation (warps 0-15) ----
        if (w < 16) {
            float acc0 = 0.f, acc1 = 0.f, d2 = 0.f, d3 = 0.f;
            const uint32_t abase = actB + lds_lane + OFF_XC * 2;
            const uint2* fb = (const uint2*)(wsm + 32768);               // smem-staged
            #pragma unroll
            for (int s2 = 0; s2 < 4; ++s2) {
                uint32_t a0, a2, a0b, a2b;
                ldsm4(abase + s2 * 64, a0, a2, a0b, a2b);
                int s = s2 * 2;
                uint2 b0 = fb[(w * 8 + s) * 32 + tl];
                uint2 b1 = fb[(w * 8 + s + 1) * 32 + tl];
                mma1(acc0, acc1, d2, d3, a0, a2, b0.x, b0.y);
                mma1(acc0, acc1, d2, d3, a0b, a2b, b1.x, b1.y);
            }
            int n0 = w * 8 + c4 * 2;
            const int gbase = rowbase * (TT * DD) + rr * (TT * DD) + t * DD;
            float cc2[2];
            #pragma unroll
            for (int c = 0; c < 2; ++c) {
                int n = n0 + c;
                float zv = ((c == 0) ? acc0 : acc1) + biasS[BS_BF + n];
                float xhv = (c == 0) ? xh0 : xh1;
                float a = al[n * 8 + rr];
                float mv = msa[n * 8 + rr], xv = xs[n * 8 + rr];
                float ch = a * zv + (1.f - a) * xhv;
                float cc = mv * xv + (1.f - mv) * ch;
                actH[rr * PH + Wp + n] = __float2half(cc);
                cc2[c] = cc;
            }
            *(float2*)&out_imp[gbase + n0] = make_float2(cc2[0], cc2[1]);
        }
        __syncthreads();                           // B4

        // ---- phase 5: commit t+1 inputs, gates MMA, fused LSTM update ----
        {
            // head: commit step t+1 into parity window Wq + side regions
            if (t + 1 < TT) {
                int si = k1 * 8 + r1;
                xs[si] = pv; msa[si] = pm;
                __half mh = __float2half(pm);
                actH[r1 * PH + OFF_MC + k1] = mh;
                actH[r1 * PH + Wq + 128 + k1] = mh;
                actH[r1 * PH + OFF_DS + k1] = __float2half(pd);
            }
            if (t + 2 < TT) {
                int g = rowbase * (TT * DD) + r1 * (TT * DD) + (t + 2) * DD + k1;
                pv = values[g]; pm = (float)masks[g]; pd = deltas[g];
            }

            float acc[4][2];                       // u = gate (i,f,g,o)
            #pragma unroll
            for (int u = 0; u < 4; ++u) { acc[u][0] = 0.f; acc[u][1] = 0.f; }
            float d2 = 0.f, d3 = 0.f;
            const uint4* fragbase = (const uint4*)g_wtb_u + (size_t)w * 2048 + tl;
            const uint32_t abase = actB + lds_lane + Wp * 2;
            #pragma unroll 4
            for (int s2 = 0; s2 < 16; ++s2) {
                uint32_t a0, a2, a0b, a2b;
                ldsm4(abase + s2 * 64, a0, a2, a0b, a2b);
                int s = s2 * 2;
                const uint4* wp0 = fragbase + s * 64;
                uint4 q0 = wp0[0], q1 = wp0[32];
                mma1(acc[0][0], acc[0][1], d2, d3, a0, a2, q0.x, q0.y);
                mma1(acc[1][0], acc[1][1], d2, d3, a0, a2, q0.z, q0.w);
                mma1(acc[2][0], acc[2][1], d2, d3, a0, a2, q1.x, q1.y);
                mma1(acc[3][0], acc[3][1], d2, d3, a0, a2, q1.z, q1.w);
                const uint4* wp1 = fragbase + (s + 1) * 64;
                uint4 q2 = wp1[0], q3 = wp1[32];
                mma1(acc[0][0], acc[0][1], d2, d3, a0b, a2b, q2.x, q2.y);
                mma1(acc[1][0], acc[1][1], d2, d3, a0b, a2b, q2.z, q2.w);
                mma1(acc[2][0], acc[2][1], d2, d3, a0b, a2b, q3.x, q3.y);
                mma1(acc[3][0], acc[3][1], d2, d3, a0b, a2b, q3.z, q3.w);
            }
            int n0 = w * 8 + c4 * 2;
            #pragma unroll
            for (int c = 0; c < 2; ++c) {
                int n = n0 + c;
                // i/f/o pre-activations are pre-halved (weights+bias); sig = 0.5*tanh+0.5
                float ig = fmaf(tanha(acc[0][c] + biasS[BS_GB + n]),       0.5f, 0.5f);
                float fg = fmaf(tanha(acc[1][c] + biasS[BS_GB + 256 + n]), 0.5f, 0.5f);
                float gg = tanha(acc[2][c] + biasS[BS_GB + 512 + n]);
                float og = fmaf(tanha(acc[3][c] + biasS[BS_GB + 768 + n]), 0.5f, 0.5f);
                float cn = fg * csr[c] + ig * gg;
                csr[c] = cn;
                hs[n * 8 + rr] = og * tanha(cn);
            }
        }
        __syncthreads();                           // B5
    }

    // ---- final: y_h = h@Wo.T + bo ----
    if (j < NROWS * CCLS) {
        int r = j >> 1, cl = j & 1;
        float acc = bo[cl];
        #pragma unroll 8
        for (int k = 0; k < HH; ++k) acc += hs[k * 8 + r] * Wo[cl * HH + k];
        out[(rowbase + r) * CCLS + cl] = acc;
    }
}

extern "C" void kernel_launch(void* const* d_in, const int* in_sizes, int n_in,
                              void* d_out, int out_size) {
    const float* values = (const float*)d_in[0];
    const int*   masks  = (const int*)  d_in[1];
    const float* deltas = (const float*)d_in[2];
    const float* Wdh = (const float*)d_in[3];
    const float* bdh = (const float*)d_in[4];
    const float* Wdx = (const float*)d_in[5];
    const float* bdx = (const float*)d_in[6];
    const float* Wh  = (const float*)d_in[7];
    const float* bh  = (const float*)d_in[8];
    const float* Wf  = (const float*)d_in[9];
    const float* bf_ = (const float*)d_in[10];
    const float* Wc  = (const float*)d_in[11];
    const float* bc  = (const float*)d_in[12];
    const float* Wih = (const float*)d_in[13];
    const float* bih = (const float*)d_in[14];
    const float* Whh = (const float*)d_in[15];
    const float* bhh = (const float*)d_in[16];
    const float* Wo  = (const float*)d_in[17];
    const float* bo  = (const float*)d_in[18];
    float* out = (float*)d_out;

    prep_kernel<<<(PREP_TOTAL + 255) / 256, 256>>>(Wdh, Wdx, Wh, Wf, Wc, Wih, Whh, bih, bhh);

    // smem: wsm 163840 B + biasS 7168 B + floats 20480 B + actH 24704 B = 216192 B
    size_t smem_bytes = (size_t)WSM_U32 * 4 + 1792 * 4 + 5120 * 4 + 8 * PH * sizeof(__half);
    cudaFuncSetAttribute(rits_kernel, cudaFuncAttributeMaxDynamicSharedMemorySize,
                         (int)smem_bytes);
    rits_kernel<<<NCTA, NTHR, smem_bytes>>>(values, masks, deltas,
                                            bdh, bdx, bh, bf_, bc,
                                            Wo, bo, out);
}

// round 17
// speedup vs baseline: 1.0363x; 1.0309x over previous
#include <cuda_runtime.h>
#include <cuda_bf16.h>
#include <cuda_fp16.h>
#include <cstdint>

// Problem dims
#define BB 1024
#define TT 512
#define DD 128
#define HH 256
#define CCLS 2
#define NROWS 8
#define NCTA (BB / NROWS)   // 128 CTAs
#define NTHR 1024

// ---- fragment-packed fp16 weights (device global; no allocations allowed) ----
// Gates [0, 262144) u32, gate-fused layout (32 warps):
//   i = (((w*32 + s)*2 + v)*128 + t*4 + e,  u = v*2 + (e>>1), j2 = e&1
//   warp w owns h-cols [w*8, w*8+8); tile u = gate index (0=i,1=f,2=g,3=o)
//   k0 = s*16 + (t&3)*2 + j2*8,  N = u*256 + w*8 + (t>>2)
//   val = half2(W[k0][N], W[k0+1][N]),  W[k][N] = k<256 ? Wih[N][k] : Whh[N][k-256]
//   NOTE: i/f/o gate weights (u != 2) pre-scaled by 0.5 (exact in fp16):
//   sigmoid(x) = 0.5*tanh.approx(x/2) + 0.5 needs no runtime halving.
// Small GEMM fragments (uint2 per (lane,tile,step)):
//   G1 (gamma_h|gamma_x: K=128, N=384):  i=((cw*8+s)*3+cu)*64 + t*2 + j2, T=cw*3+cu
//   G2a (x_h: K=256,N=128):  i=((wl*16+s)*2+uu)*64 + t*2 + j2, T=wl*2+uu
//   G2b (alpha: K=256,N=128): same layout, separate base
//   G3 (z_h: K=128,N=128): i=(T*8+s)*64 + t*2 + j2
// G1 and G3 are read with L1::evict_last -> L1D-resident across steps (128 KB,
// fits the ~183 KB carveout at 45 KB smem). Gates/G2 stream with default policy.
#define SMG1  262144
#define SMG2A 286720
#define SMG2B 303104
#define SMG3  319488
#define WTB_TOTAL 327680
__device__ uint32_t g_wtb_u[WTB_TOTAL];
// Combined gate bias bih+bhh (i/f/o pre-scaled by 0.5)
__device__ float g_gb[4 * HH];

// 1-MUFU tanh (sm_75+): max rel err ~2^-11
__device__ __forceinline__ float tanha(float x) {
    float y; asm("tanh.approx.f32 %0, %1;" : "=f"(y) : "f"(x)); return y;
}

// m16n8k16 HMMA; A rows 8-15 zero, c2/c3 discarded.
__device__ __forceinline__ void mma1(float& c0, float& c1, float& c2, float& c3,
                                     uint32_t a0, uint32_t a2, uint32_t b0, uint32_t b1) {
    asm volatile(
        "mma.sync.aligned.m16n8k16.row.col.f32.f16.f16.f32 "
        "{%0,%1,%2,%3}, {%4,%5,%6,%7}, {%8,%9}, {%0,%1,%2,%3};"
        : "+f"(c0), "+f"(c1), "+f"(c2), "+f"(c3)
        : "r"(a0), "r"(0u), "r"(a2), "r"(0u), "r"(b0), "r"(b1));
}

// ldmatrix x4: loads a0(s), a2(s), a0(s+1), a2(s+1) for two consecutive k-steps.
__device__ __forceinline__ void ldsm4(uint32_t addr, uint32_t& r0, uint32_t& r1,
                                      uint32_t& r2, uint32_t& r3) {
    asm volatile("ldmatrix.sync.aligned.m8n8.x4.shared.b16 {%0,%1,%2,%3}, [%4];"
        : "=r"(r0), "=r"(r1), "=r"(r2), "=r"(r3) : "r"(addr));
}

// L1-persistent uint2 load (read-only data, evict-last priority)
__device__ __forceinline__ uint2 ldg2_el(const uint2* p) {
    uint2 v;
    asm volatile("ld.global.nc.L1::evict_last.v2.u32 {%0,%1}, [%2];"
        : "=r"(v.x), "=r"(v.y) : "l"(p));
    return v;
}

__device__ __forceinline__ uint32_t pack_pair(float lo, float hi) {
    uint32_t l = __half_as_ushort(__float2half_rn(lo));
    uint32_t h = __half_as_ushort(__float2half_rn(hi));
    return l | (h << 16);
}

// ---- fused prologue: all fragment packing + bias combine, ONE launch ----
#define PREP_TOTAL (WTB_TOTAL + 1024)
__global__ void prep_kernel(const float* __restrict__ Wdh, const float* __restrict__ Wdx,
                            const float* __restrict__ Wh,  const float* __restrict__ Wf,
                            const float* __restrict__ Wc,  const float* __restrict__ Wih,
                            const float* __restrict__ Whh, const float* __restrict__ bih,
                            const float* __restrict__ bhh) {
    int idx = blockIdx.x * blockDim.x + threadIdx.x;
    if (idx >= PREP_TOTAL) return;
    if (idx < 262144) {                    // gates, gate-fused coalesced layout
        int e = idx & 3, t = (idx >> 2) & 31, v = (idx >> 7) & 1;
        int s = (idx >> 8) & 31, w = (idx >> 13) & 31;
        int u = v * 2 + (e >> 1), j2 = e & 1;
        int k0 = s * 16 + (t & 3) * 2 + j2 * 8;
        int N  = u * 256 + w * 8 + (t >> 2);
        float lo, hi;
        if (k0 < 256) { lo = Wih[N * 256 + k0];       hi = Wih[N * 256 + k0 + 1]; }
        else          { lo = Whh[N * 256 + k0 - 256]; hi = Whh[N * 256 + k0 - 255]; }
        if (u != 2) { lo *= 0.5f; hi *= 0.5f; }     // i/f/o: fold sigmoid x/2
        g_wtb_u[idx] = pack_pair(lo, hi);
    } else if (idx < SMG2A) {              // G1
        int i = idx - SMG1;
        int j2 = i & 1, t = (i >> 1) & 31;
        int rest = i >> 6, uu = rest % 3, ws = rest / 3;
        int s = ws & 7, w = ws >> 3;
        int tile = w * 3 + uu;
        int n = tile * 8 + (t >> 2);
        int k0 = s * 16 + (t & 3) * 2 + j2 * 8;
        float lo, hi;
        if (n < 256) { lo = Wdh[n * 128 + k0]; hi = Wdh[n * 128 + k0 + 1]; }
        else { int n2 = n - 256; lo = Wdx[n2 * 128 + k0]; hi = Wdx[n2 * 128 + k0 + 1]; }
        g_wtb_u[idx] = pack_pair(lo, hi);
    } else if (idx < SMG2B) {              // G2a: Wh
        int i = idx - SMG2A;
        int j2 = i & 1, t = (i >> 1) & 31;
        int rest = i >> 6, uu = rest & 1, ws = rest >> 1;
        int s = ws & 15, w = ws >> 4;
        int n = (w * 2 + uu) * 8 + (t >> 2);
        int k0 = s * 16 + (t & 3) * 2 + j2 * 8;
        g_wtb_u[idx] = pack_pair(Wh[n * 256 + k0], Wh[n * 256 + k0 + 1]);
    } else if (idx < SMG3) {               // G2b: Wc (input = gx || m)
        int i = idx - SMG2B;
        int j2 = i & 1, t = (i >> 1) & 31;
        int rest = i >> 6, uu = rest & 1, ws = rest >> 1;
        int s = ws & 15, w = ws >> 4;
        int n = (w * 2 + uu) * 8 + (t >> 2);
        int k0 = s * 16 + (t & 3) * 2 + j2 * 8;
        g_wtb_u[idx] = pack_pair(Wc[n * 256 + k0], Wc[n * 256 + k0 + 1]);
    } else if (idx < WTB_TOTAL) {          // G3: Wf
        int i = idx - SMG3;
        int j2 = i & 1, t = (i >> 1) & 31;
        int rest = i >> 6, s = rest & 7, w = rest >> 3;
        int n = w * 8 + (t >> 2);
        int k0 = s * 16 + (t & 3) * 2 + j2 * 8;
        g_wtb_u[idx] = pack_pair(Wf[n * 128 + k0], Wf[n * 128 + k0 + 1]);
    } else {                               // combined gate bias (i/f/o halved)
        int i = idx - WTB_TOTAL;
        float b = bih[i] + bhh[i];
        int gate = i >> 8;                 // 0=i,1=f,2=g,3=o
        if (gate != 2) b *= 0.5f;
        g_gb[i] = b;
    }
}

// ---- persistent RITS scan: 128 CTAs x 8 rows, 1024 threads, 4 barriers/step ----
// fp16 shadow actH[8][PH] per row:
//   W0 [0:512) / W1 [512:1024): parity gates A-window = c_c(128)|m(128)|hd(256)
//   [1024:1152) gx | [1152:1280) m_copy | [1280:1408) dsa | [1408:1536) x_c
#define PH 1544   // row stride 3088 B -> 4-bank shift per row (conflict-free LDSM)
#define OFF_GX 1024
#define OFF_MC 1152
#define OFF_DS 1280
#define OFF_XC 1408
__global__ void __launch_bounds__(NTHR, 1) rits_kernel(
    const float* __restrict__ values, const int* __restrict__ masks, const float* __restrict__ deltas,
    const float* __restrict__ bdh, const float* __restrict__ bdx,
    const float* __restrict__ bh,  const float* __restrict__ bf_,
    const float* __restrict__ bc,
    const float* __restrict__ Wo,  const float* __restrict__ bo,
    float* __restrict__ out)
{
    extern __shared__ float smem[];
    float* hs  = smem;            // [H*8]
    float* xs  = hs  + 2048;      // [D*8]
    float* msa = xs  + 1024;      // [D*8]
    float* al  = msa + 1024;      // [D*8]  alpha
    __half* actH = (__half*)(al + 1024);  // [8][PH]

    const int j = threadIdx.x;
    const int w = j >> 5, tl = j & 31;
    const int rr = tl >> 2, c4 = tl & 3;
    const int rowbase = blockIdx.x * NROWS;
    float* out_imp = out + BB * CCLS;

    // LDSM lane address base (bytes): row = tl&7, matrix idx = (tl>>3)&3 -> +0/8/16/24 halves
    const uint32_t actB = (uint32_t)__cvta_generic_to_shared(actH);
    const uint32_t lds_lane = ((tl & 7) * PH + ((tl >> 3) & 3) * 8) * 2;

    for (int i = j; i < 2048; i += NTHR) { hs[i] = 0.f; }

    // cell state lives in registers: phase-5 epilogue thread owns (n0..n0+1, rr) forever
    float csr[2] = {0.f, 0.f};

    // input prefetch (1 elem/thread)
    const int r1 = j >> 7, k1 = j & 127;
    float pv, pm, pd;
    {
        int g = rowbase * (TT * DD) + r1 * (TT * DD) + k1;
        pv = values[g]; pm = (float)masks[g]; pd = deltas[g];
    }
    // commit step 0 (window 0)
    {
        int si = k1 * 8 + r1;
        xs[si] = pv; msa[si] = pm;
        __half mh = __float2half(pm);
        actH[r1 * PH + OFF_MC + k1] = mh;
        actH[r1 * PH + 128 + k1] = mh;                 // m_gates, window 0
        actH[r1 * PH + OFF_DS + k1] = __float2half(pd);
    }
    // prefetch step 1
    {
        int g = rowbase * (TT * DD) + r1 * (TT * DD) + DD + k1;
        pv = values[g]; pm = (float)masks[g]; pd = deltas[g];
    }
    __syncthreads();

    for (int t = 0; t < TT; ++t) {
        const int Wp = (t & 1) * 512;
        const int Wq = 512 - Wp;

        // ---- phase 2 (G1): gamma_h | gamma_x; tiles T=w (all), T=32+w (w<16) ----
        {
            const uint2* fb = (const uint2*)(g_wtb_u + SMG1);
            float acc0 = 0.f, acc1 = 0.f, accB0 = 0.f, accB1 = 0.f;
            float d2 = 0.f, d3 = 0.f;
            const int cw1 = w / 3, cu1 = w - cw1 * 3;
            const int T2 = 32 + w;
            const int cw2 = T2 / 3, cu2 = T2 - cw2 * 3;
            const bool two = (w < 16);
            const uint32_t abase = actB + lds_lane + OFF_DS * 2;
            #pragma unroll
            for (int s2 = 0; s2 < 4; ++s2) {
                uint32_t a0, a2, a0b, a2b;
                ldsm4(abase + s2 * 64, a0, a2, a0b, a2b);
                int s = s2 * 2;
                uint2 b0 = ldg2_el(&fb[((cw1 * 8 + s) * 3 + cu1) * 32 + tl]);
                uint2 b1 = ldg2_el(&fb[((cw1 * 8 + s + 1) * 3 + cu1) * 32 + tl]);
                mma1(acc0, acc1, d2, d3, a0, a2, b0.x, b0.y);
                mma1(acc0, acc1, d2, d3, a0b, a2b, b1.x, b1.y);
                if (two) {
                    uint2 c0 = ldg2_el(&fb[((cw2 * 8 + s) * 3 + cu2) * 32 + tl]);
                    uint2 c1 = ldg2_el(&fb[((cw2 * 8 + s + 1) * 3 + cu2) * 32 + tl]);
                    mma1(accB0, accB1, d2, d3, a0, a2, c0.x, c0.y);
                    mma1(accB0, accB1, d2, d3, a0b, a2b, c1.x, c1.y);
                }
            }
            {
                int n0 = w * 8 + c4 * 2;
                #pragma unroll
                for (int c = 0; c < 2; ++c) {
                    int n = n0 + c;
                    float v = (c == 0) ? acc0 : acc1;
                    float gam = __expf(-fmaxf(v + bdh[n], 0.f));
                    float hv = hs[n * 8 + rr] * gam;
                    actH[rr * PH + Wp + 256 + n] = __float2half(hv);
                }
            }
            if (two) {
                int n0 = T2 * 8 - 256 + c4 * 2;
                #pragma unroll
                for (int c = 0; c < 2; ++c) {
                    int n2 = n0 + c;
                    float v = (c == 0) ? accB0 : accB1;
                    float gxv = __expf(-fmaxf(v + bdx[n2], 0.f));
                    actH[rr * PH + OFF_GX + n2] = __float2half(gxv);
                }
            }
        }
        __syncthreads();                           // B2

        // ---- phase 3 (G2): x_h + x_c (warps 0-15) | alpha (warps 16-31) ----
        float xh0 = 0.f, xh1 = 0.f;                // live across B3 into phase 4
        {
            const bool isA = (w < 16);
            const int T = isA ? w : (w - 16);
            const int wl = T >> 1, uu = T & 1;
            const uint32_t abase = actB + lds_lane
                                 + (isA ? (Wp + 256) : OFF_GX) * 2;
            const uint2* fb = (const uint2*)(g_wtb_u + (isA ? SMG2A : SMG2B));
            float acc0 = 0.f, acc1 = 0.f, d2 = 0.f, d3 = 0.f;
            #pragma unroll
            for (int s2 = 0; s2 < 8; ++s2) {
                uint32_t a0, a2, a0b, a2b;
                ldsm4(abase + s2 * 64, a0, a2, a0b, a2b);
                int s = s2 * 2;
                uint2 b0 = fb[((wl * 16 + s) * 2 + uu) * 32 + tl];
                uint2 b1 = fb[((wl * 16 + s + 1) * 2 + uu) * 32 + tl];
                mma1(acc0, acc1, d2, d3, a0, a2, b0.x, b0.y);
                mma1(acc0, acc1, d2, d3, a0b, a2b, b1.x, b1.y);
            }
            int n0 = T * 8 + c4 * 2;
            if (isA) {
                xh0 = acc0 + bh[n0];
                xh1 = acc1 + bh[n0 + 1];
                float m0 = msa[n0 * 8 + rr],       x0 = xs[n0 * 8 + rr];
                float m1 = msa[(n0 + 1) * 8 + rr], x1 = xs[(n0 + 1) * 8 + rr];
                actH[rr * PH + OFF_XC + n0]     = __float2half(m0 * x0 + (1.f - m0) * xh0);
                actH[rr * PH + OFF_XC + n0 + 1] = __float2half(m1 * x1 + (1.f - m1) * xh1);
            } else {
                al[n0 * 8 + rr]       = acc0 + bc[n0];
                al[(n0 + 1) * 8 + rr] = acc1 + bc[n0 + 1];
            }
        }
        __syncthreads();                           // B3

        // ---- phase 4 (G3): z_h + c_h + c_c + imputation (warps 0-15) ----
        if (w < 16) {
            float acc0 = 0.f, acc1 = 0.f, d2 = 0.f, d3 = 0.f;
            const uint32_t abase = actB + lds_lane + OFF_XC * 2;
            const uint2* fb = (const uint2*)(g_wtb_u + SMG3);
            #pragma unroll
            for (int s2 = 0; s2 < 4; ++s2) {
                uint32_t a0, a2, a0b, a2b;
                ldsm4(abase + s2 * 64, a0, a2, a0b, a2b);
                int s = s2 * 2;
                uint2 b0 = ldg2_el(&fb[(w * 8 + s) * 32 + tl]);
                uint2 b1 = ldg2_el(&fb[(w * 8 + s + 1) * 32 + tl]);
                mma1(acc0, acc1, d2, d3, a0, a2, b0.x, b0.y);
                mma1(acc0, acc1, d2, d3, a0b, a2b, b1.x, b1.y);
            }
            int n0 = w * 8 + c4 * 2;
            const int gbase = rowbase * (TT * DD) + rr * (TT * DD) + t * DD;
            float cc2[2];
            #pragma unroll
            for (int c = 0; c < 2; ++c) {
                int n = n0 + c;
                float zv = ((c == 0) ? acc0 : acc1) + bf_[n];
                float xhv = (c == 0) ? xh0 : xh1;
                float a = al[n * 8 + rr];
                float mv = msa[n * 8 + rr], xv = xs[n * 8 + rr];
                float ch = a * zv + (1.f - a) * xhv;
                float cc = mv * xv + (1.f - mv) * ch;
                actH[rr * PH + Wp + n] = __float2half(cc);
                cc2[c] = cc;
            }
            *(float2*)&out_imp[gbase + n0] = make_float2(cc2[0], cc2[1]);
        }
        __syncthreads();                           // B4

        // ---- phase 5: commit t+1 inputs, gates MMA, fused LSTM update ----
        {
            // head: commit step t+1 into parity window Wq + side regions
            if (t + 1 < TT) {
                int si = k1 * 8 + r1;
                xs[si] = pv; msa[si] = pm;
                __half mh = __float2half(pm);
                actH[r1 * PH + OFF_MC + k1] = mh;
                actH[r1 * PH + Wq + 128 + k1] = mh;
                actH[r1 * PH + OFF_DS + k1] = __float2half(pd);
            }
            if (t + 2 < TT) {
                int g = rowbase * (TT * DD) + r1 * (TT * DD) + (t + 2) * DD + k1;
                pv = values[g]; pm = (float)masks[g]; pd = deltas[g];
            }

            float acc[4][2];                       // u = gate (i,f,g,o)
            #pragma unroll
            for (int u = 0; u < 4; ++u) { acc[u][0] = 0.f; acc[u][1] = 0.f; }
            float d2 = 0.f, d3 = 0.f;
            const uint4* fragbase = (const uint4*)g_wtb_u + (size_t)w * 2048 + tl;
            const uint32_t abase = actB + lds_lane + Wp * 2;
            #pragma unroll 8
            for (int s2 = 0; s2 < 16; ++s2) {
                uint32_t a0, a2, a0b, a2b;
                ldsm4(abase + s2 * 64, a0, a2, a0b, a2b);
                int s = s2 * 2;
                const uint4* wp0 = fragbase + s * 64;
                uint4 q0 = wp0[0], q1 = wp0[32];
                mma1(acc[0][0], acc[0][1], d2, d3, a0, a2, q0.x, q0.y);
                mma1(acc[1][0], acc[1][1], d2, d3, a0, a2, q0.z, q0.w);
                mma1(acc[2][0], acc[2][1], d2, d3, a0, a2, q1.x, q1.y);
                mma1(acc[3][0], acc[3][1], d2, d3, a0, a2, q1.z, q1.w);
                const uint4* wp1 = fragbase + (s + 1) * 64;
                uint4 q2 = wp1[0], q3 = wp1[32];
                mma1(acc[0][0], acc[0][1], d2, d3, a0b, a2b, q2.x, q2.y);
                mma1(acc[1][0], acc[1][1], d2, d3, a0b, a2b, q2.z, q2.w);
                mma1(acc[2][0], acc[2][1], d2, d3, a0b, a2b, q3.x, q3.y);
                mma1(acc[3][0], acc[3][1], d2, d3, a0b, a2b, q3.z, q3.w);
            }
            int n0 = w * 8 + c4 * 2;
            #pragma unroll
            for (int c = 0; c < 2; ++c) {
                int n = n0 + c;
                // i/f/o pre-activations are pre-halved (weights+bias); sig = 0.5*tanh+0.5
                float ig = fmaf(tanha(acc[0][c] + g_gb[n]),       0.5f, 0.5f);
                float fg = fmaf(tanha(acc[1][c] + g_gb[256 + n]), 0.5f, 0.5f);
                float gg = tanha(acc[2][c] + g_gb[512 + n]);
                float og = fmaf(tanha(acc[3][c] + g_gb[768 + n]), 0.5f, 0.5f);
                float cn = fg * csr[c] + ig * gg;
                csr[c] = cn;
                hs[n * 8 + rr] = og * tanha(cn);
            }
        }
        __syncthreads();                           // B5
    }

    // ---- final: y_h = h@Wo.T + bo ----
    if (j < NROWS * CCLS) {
        int r = j >> 1, cl = j & 1;
        float acc = bo[cl];
        #pragma unroll 8
        for (int k = 0; k < HH; ++k) acc += hs[k * 8 + r] * Wo[cl * HH + k];
        out[(rowbase + r) * CCLS + cl] = acc;
    }
}

extern "C" void kernel_launch(void* const* d_in, const int* in_sizes, int n_in,
                              void* d_out, int out_size) {
    const float* values = (const float*)d_in[0];
    const int*   masks  = (const int*)  d_in[1];
    const float* deltas = (const float*)d_in[2];
    const float* Wdh = (const float*)d_in[3];
    const float* bdh = (const float*)d_in[4];
    const float* Wdx = (const float*)d_in[5];
    const float* bdx = (const float*)d_in[6];
    const float* Wh  = (const float*)d_in[7];
    const float* bh  = (const float*)d_in[8];
    const float* Wf  = (const float*)d_in[9];
    const float* bf_ = (const float*)d_in[10];
    const float* Wc  = (const float*)d_in[11];
    const float* bc  = (const float*)d_in[12];
    const float* Wih = (const float*)d_in[13];
    const float* bih = (const float*)d_in[14];
    const float* Whh = (const float*)d_in[15];
    const float* bhh = (const float*)d_in[16];
    const float* Wo  = (const float*)d_in[17];
    const float* bo  = (const float*)d_in[18];
    float* out = (float*)d_out;

    prep_kernel<<<(PREP_TOTAL + 255) / 256, 256>>>(Wdh, Wdx, Wh, Wf, Wc, Wih, Whh, bih, bhh);

    // smem: 5120 floats (20480 B) + actH 8*1544 halves (24704 B) = 45184 B
    size_t smem_bytes = 5120 * sizeof(float) + 8 * PH * sizeof(__half);
    cudaFuncSetAttribute(rits_kernel, cudaFuncAttributeMaxDynamicSharedMemorySize,
                         (int)smem_bytes);
    rits_kernel<<<NCTA, NTHR, smem_bytes>>>(values, masks, deltas,
                                            bdh, bdx, bh, bf_, bc,
                                            Wo, bo, out);
}